// round 11
// baseline (speedup 1.0000x reference)
#include <cuda_runtime.h>
#include <cuda_fp16.h>
#include <cstdint>

#define N_NODES 50000
#define N_EDGES 600000
#define DIM 128
#define TOT_EDGES (N_EDGES + N_NODES)   // edges + self loops
#define NB 196                          // ceil(50000/256) scan blocks

// smem tiles: halves, row stride 136 (272B = 16B-aligned, conflict-free frags)
#define STRH 136                        // stride in halves
#define STRW 68                         // stride in u32 words
#define SMEM_BYTES (2 * 128 * STRH * 2) // As + Wt = 69632 B

// ---- scratch (device globals; no allocations allowed) ----
__device__ __half g_hw  [N_NODES * DIM];  // h @ W          (fp16)
__device__ __half g_act [N_NODES * DIM];  // relu(agg + b)  (fp16)
__device__ float  g_dinv[N_NODES];
__device__ int    g_deg   [N_NODES];
__device__ int    g_rowptr[N_NODES + 1];
__device__ int    g_cursor[N_NODES];
__device__ int    g_bsum  [NB];
__device__ int    g_esrc  [TOT_EDGES];    // CSR-by-dst: src node per slot
__device__ float  g_enorm [TOT_EDGES];    // dinv[src]*dinv[dst] per slot

// ---------------------------------------------------------------------------
// CSR build: degree -> block sums -> finalize (inline top-scan) -> fill
// ---------------------------------------------------------------------------
__global__ void deg_init_k() {
    int i = blockIdx.x * blockDim.x + threadIdx.x;
    if (i < N_NODES) g_deg[i] = 1;          // self loop
}

__global__ void deg_count_k(const int* __restrict__ ei) {
    int e4 = blockIdx.x * blockDim.x + threadIdx.x;   // int4 task
    if (e4 * 4 + 3 < N_EDGES) {
        int4 d = *(const int4*)(ei + N_EDGES + e4 * 4);
        if (d.x >= 0 && d.x < N_NODES) atomicAdd(&g_deg[d.x], 1);
        if (d.y >= 0 && d.y < N_NODES) atomicAdd(&g_deg[d.y], 1);
        if (d.z >= 0 && d.z < N_NODES) atomicAdd(&g_deg[d.z], 1);
        if (d.w >= 0 && d.w < N_NODES) atomicAdd(&g_deg[d.w], 1);
    } else {
        for (int e = e4 * 4; e < N_EDGES; e++) {
            int d = ei[N_EDGES + e];
            if (d >= 0 && d < N_NODES) atomicAdd(&g_deg[d], 1);
        }
    }
}

__global__ void __launch_bounds__(256) bsum_k() {
    __shared__ int sh[256];
    int i = blockIdx.x * 256 + threadIdx.x;
    sh[threadIdx.x] = (i < N_NODES) ? g_deg[i] : 0;
    __syncthreads();
    for (int off = 128; off > 0; off >>= 1) {
        if (threadIdx.x < off) sh[threadIdx.x] += sh[threadIdx.x + off];
        __syncthreads();
    }
    if (threadIdx.x == 0) g_bsum[blockIdx.x] = sh[0];
}

__global__ void __launch_bounds__(256) finalize_k() {
    __shared__ int sh[256];
    __shared__ int blkoff;
    int i = blockIdx.x * 256 + threadIdx.x;
    int t = threadIdx.x;

    sh[t] = (t < NB && t < blockIdx.x) ? g_bsum[t] : 0;
    __syncthreads();
    for (int off = 128; off > 0; off >>= 1) {
        if (t < off) sh[t] += sh[t + off];
        __syncthreads();
    }
    if (t == 0) blkoff = sh[0];
    __syncthreads();

    int v = (i < N_NODES) ? g_deg[i] : 0;
    sh[t] = v;
    __syncthreads();
    for (int off = 1; off < 256; off <<= 1) {
        int x = (t >= off) ? sh[t - off] : 0;
        __syncthreads();
        sh[t] += x;
        __syncthreads();
    }
    if (i < N_NODES) {
        int start = blkoff + sh[t] - v;     // exclusive global prefix
        g_rowptr[i] = start;
        g_cursor[i] = start;
        g_dinv[i]   = rsqrtf((float)v);
        if (i == N_NODES - 1) g_rowptr[N_NODES] = start + v;
    }
}

__global__ void fill_k(const int* __restrict__ ei) {
    int e = blockIdx.x * blockDim.x + threadIdx.x;
    if (e >= TOT_EDGES) return;
    int s, d;
    if (e < N_EDGES) {
        s = ei[e];
        d = ei[N_EDGES + e];
        if (s < 0 || s >= N_NODES || d < 0 || d >= N_NODES) return;
    } else {
        s = d = e - N_EDGES;                // self loop
    }
    int pos = atomicAdd(&g_cursor[d], 1);
    g_esrc[pos]  = s;
    g_enorm[pos] = g_dinv[s] * g_dinv[d];
}

// ---------------------------------------------------------------------------
// fp16 tensor-core GEMM: g_hw[N,128] (fp16) = src @ W[128,128]
//   use_agg=0: src = x (fp32);  use_agg=1: src = g_act (fp16)
// Full-K single-stage smem; mma.m16n8k16.f32.f16.f16.f32.
// 8 warps (4M x 2N), warp tile 32x64.
// ---------------------------------------------------------------------------
extern __shared__ uint32_t s_dyn[];

__global__ void __launch_bounds__(256) gemm_f16_k(
    const float* __restrict__ A, const float* __restrict__ W, int use_agg)
{
    uint32_t* As = s_dyn;                 // [128][STRW] u32 (2 halves each)
    uint32_t* Wt = s_dyn + 128 * STRW;    // [128 n][STRW] u32, k contiguous

    const int tid   = threadIdx.x;
    const int lane  = tid & 31;
    const int wid   = tid >> 5;
    const int warpM = wid & 3;            // 0..3  -> 32-row strip
    const int warpN = wid >> 2;           // 0..1  -> 64-col strip
    const int g     = lane >> 2;          // groupID 0..7
    const int q     = lane & 3;           // thread-in-group 0..3
    const int row0  = blockIdx.x * 128;

    // ---- load A (full K=128) as fp16 ----
    if (!use_agg) {
#pragma unroll
        for (int t = 0; t < 16; t++) {
            int i  = tid + t * 256;       // 0..4095 float4 tasks
            int r  = i >> 5;              // 0..127
            int c4 = (i & 31) * 4;        // 0..124
            int grow = row0 + r;
            float4 v = make_float4(0.f, 0.f, 0.f, 0.f);
            if (grow < N_NODES)
                v = *(const float4*)(A + (size_t)grow * DIM + c4);
            uint2 p;
            *(__half2*)&p.x = __float22half2_rn(make_float2(v.x, v.y));
            *(__half2*)&p.y = __float22half2_rn(make_float2(v.z, v.w));
            *(uint2*)&As[r * STRW + c4 / 2] = p;
        }
    } else {
#pragma unroll
        for (int t = 0; t < 8; t++) {
            int i  = tid + t * 256;       // 0..2047 uint4 tasks (8 halves)
            int r  = i >> 4;              // 0..127
            int c8 = (i & 15) * 8;        // 0..120
            int grow = row0 + r;
            uint4 raw = make_uint4(0, 0, 0, 0);
            if (grow < N_NODES)
                raw = *(const uint4*)(g_act + (size_t)grow * DIM + c8);
            *(uint4*)&As[r * STRW + c8 / 2] = raw;
        }
    }

    // ---- load W transposed: Wt[n][k], coalesced LDG per k, packed STS.64 ----
#pragma unroll
    for (int t = 0; t < 16; t++) {
        int i  = tid + t * 256;           // 0..4095 tasks: (n, k-block of 4)
        int n  = i & 127;
        int kb = i >> 7;                  // 0..31
        int k0 = kb * 4;
        float w0 = W[(size_t)(k0 + 0) * DIM + n];
        float w1 = W[(size_t)(k0 + 1) * DIM + n];
        float w2 = W[(size_t)(k0 + 2) * DIM + n];
        float w3 = W[(size_t)(k0 + 3) * DIM + n];
        uint2 p;
        *(__half2*)&p.x = __float22half2_rn(make_float2(w0, w1));
        *(__half2*)&p.y = __float22half2_rn(make_float2(w2, w3));
        *(uint2*)&Wt[n * STRW + kb * 2] = p;
    }
    __syncthreads();

    // ---- mma: 8 k-steps of 16 ----
    float acc[2][8][4];
#pragma unroll
    for (int mt = 0; mt < 2; mt++)
#pragma unroll
        for (int nt = 0; nt < 8; nt++)
#pragma unroll
            for (int i = 0; i < 4; i++) acc[mt][nt][i] = 0.0f;

#pragma unroll
    for (int ks = 0; ks < 8; ++ks) {
        const int kw = ks * 8;            // u32 k-offset (16 halves)

        uint32_t a[2][4];
#pragma unroll
        for (int mt = 0; mt < 2; mt++) {
            int mb = warpM * 32 + mt * 16 + g;
            a[mt][0] = As[mb * STRW + kw + q];
            a[mt][1] = As[(mb + 8) * STRW + kw + q];
            a[mt][2] = As[mb * STRW + kw + q + 4];
            a[mt][3] = As[(mb + 8) * STRW + kw + q + 4];
        }
        uint32_t b[8][2];
#pragma unroll
        for (int nt = 0; nt < 8; nt++) {
            int n = warpN * 64 + nt * 8 + g;
            b[nt][0] = Wt[n * STRW + kw + q];
            b[nt][1] = Wt[n * STRW + kw + q + 4];
        }
#pragma unroll
        for (int mt = 0; mt < 2; mt++)
#pragma unroll
            for (int nt = 0; nt < 8; nt++) {
                asm volatile(
                    "mma.sync.aligned.m16n8k16.row.col.f32.f16.f16.f32 "
                    "{%0,%1,%2,%3}, {%4,%5,%6,%7}, {%8,%9}, {%0,%1,%2,%3};"
                    : "+f"(acc[mt][nt][0]), "+f"(acc[mt][nt][1]),
                      "+f"(acc[mt][nt][2]), "+f"(acc[mt][nt][3])
                    : "r"(a[mt][0]), "r"(a[mt][1]), "r"(a[mt][2]), "r"(a[mt][3]),
                      "r"(b[nt][0]), "r"(b[nt][1]));
            }
    }

    // ---- epilogue: write fp16 hw ----
#pragma unroll
    for (int mt = 0; mt < 2; mt++) {
        int r0 = row0 + warpM * 32 + mt * 16 + g;
        int r1 = r0 + 8;
#pragma unroll
        for (int nt = 0; nt < 8; nt++) {
            int col = warpN * 64 + nt * 8 + q * 2;
            if (r0 < N_NODES)
                *(__half2*)(g_hw + (size_t)r0 * DIM + col) =
                    __float22half2_rn(make_float2(acc[mt][nt][0], acc[mt][nt][1]));
            if (r1 < N_NODES)
                *(__half2*)(g_hw + (size_t)r1 * DIM + col) =
                    __float22half2_rn(make_float2(acc[mt][nt][2], acc[mt][nt][3]));
        }
    }
}

// ---------------------------------------------------------------------------
// gather: warp per dst node; lane owns 4 halves (8B) of the 256B row.
// acc = bias; acc += hw[src]*norm (fp32 math); relu;
// last=0 -> write fp16 g_act; last=1 -> write fp32 out.
// ---------------------------------------------------------------------------
__global__ void __launch_bounds__(256) gather_k(
    const float* __restrict__ bias, float* __restrict__ out, int last)
{
    int w    = (blockIdx.x * blockDim.x + threadIdx.x) >> 5;
    int lane = threadIdx.x & 31;
    if (w >= N_NODES) return;

    int beg = g_rowptr[w];
    int end = g_rowptr[w + 1];

    float4 acc = ((const float4*)bias)[lane];
    const uint2* hw2 = (const uint2*)g_hw;   // 4 halves per lane-slot

    int j = beg;
    for (; j + 3 < end; j += 4) {
        int   s0 = g_esrc[j],      s1 = g_esrc[j + 1];
        int   s2 = g_esrc[j + 2],  s3 = g_esrc[j + 3];
        float n0 = g_enorm[j],     n1 = g_enorm[j + 1];
        float n2 = g_enorm[j + 2], n3 = g_enorm[j + 3];
        uint2 r0 = hw2[s0 * 32 + lane];
        uint2 r1 = hw2[s1 * 32 + lane];
        uint2 r2 = hw2[s2 * 32 + lane];
        uint2 r3 = hw2[s3 * 32 + lane];
        float2 a0 = __half22float2(*(__half2*)&r0.x), b0 = __half22float2(*(__half2*)&r0.y);
        float2 a1 = __half22float2(*(__half2*)&r1.x), b1 = __half22float2(*(__half2*)&r1.y);
        float2 a2 = __half22float2(*(__half2*)&r2.x), b2 = __half22float2(*(__half2*)&r2.y);
        float2 a3 = __half22float2(*(__half2*)&r3.x), b3 = __half22float2(*(__half2*)&r3.y);
        acc.x += a0.x * n0; acc.y += a0.y * n0; acc.z += b0.x * n0; acc.w += b0.y * n0;
        acc.x += a1.x * n1; acc.y += a1.y * n1; acc.z += b1.x * n1; acc.w += b1.y * n1;
        acc.x += a2.x * n2; acc.y += a2.y * n2; acc.z += b2.x * n2; acc.w += b2.y * n2;
        acc.x += a3.x * n3; acc.y += a3.y * n3; acc.z += b3.x * n3; acc.w += b3.y * n3;
    }
    for (; j < end; j++) {
        int   s0 = g_esrc[j];
        float n0 = g_enorm[j];
        uint2 r0 = hw2[s0 * 32 + lane];
        float2 a0 = __half22float2(*(__half2*)&r0.x), b0 = __half22float2(*(__half2*)&r0.y);
        acc.x += a0.x * n0; acc.y += a0.y * n0; acc.z += b0.x * n0; acc.w += b0.y * n0;
    }

    acc.x = fmaxf(acc.x, 0.f); acc.y = fmaxf(acc.y, 0.f);
    acc.z = fmaxf(acc.z, 0.f); acc.w = fmaxf(acc.w, 0.f);

    if (last) {
        ((float4*)out)[w * 32 + lane] = acc;
    } else {
        uint2 o;
        *(__half2*)&o.x = __float22half2_rn(make_float2(acc.x, acc.y));
        *(__half2*)&o.y = __float22half2_rn(make_float2(acc.z, acc.w));
        ((uint2*)g_act)[w * 32 + lane] = o;
    }
}

// ---------------------------------------------------------------------------
extern "C" void kernel_launch(void* const* d_in, const int* in_sizes, int n_in,
                              void* d_out, int out_size)
{
    const float* x  = (const float*)d_in[0];
    const int*   ei = (const int*)d_in[1];     // edge_index int32 [2, E]
    const float* W0 = (const float*)d_in[2];
    const float* b0 = (const float*)d_in[3];
    const float* W1 = (const float*)d_in[4];
    const float* b1 = (const float*)d_in[5];
    const float* W2 = (const float*)d_in[6];
    const float* b2 = (const float*)d_in[7];
    float* out = (float*)d_out;

    static int inited = 0;
    static cudaStream_t s2;
    static cudaEvent_t evFork, evJoin;
    if (!inited) {
        cudaFuncSetAttribute(gemm_f16_k,
            cudaFuncAttributeMaxDynamicSharedMemorySize, SMEM_BYTES);
        cudaStreamCreateWithFlags(&s2, cudaStreamNonBlocking);
        cudaEventCreateWithFlags(&evFork, cudaEventDisableTiming);
        cudaEventCreateWithFlags(&evJoin, cudaEventDisableTiming);
        inited = 1;
    }

    const int cntBlocks  = (N_EDGES / 4 + 255) / 256;
    const int totBlocks  = (TOT_EDGES + 255) / 256;
    const int gemmBlocks = (N_NODES + 127) / 128;
    const int gathBlocks = (N_NODES * 32 + 255) / 256;   // warp per node

    // fork: CSR build on s2, concurrent with layer-0 GEMM on the main stream
    cudaEventRecord(evFork, 0);
    cudaStreamWaitEvent(s2, evFork, 0);

    deg_init_k <<<NB, 256, 0, s2>>>();
    deg_count_k<<<cntBlocks, 256, 0, s2>>>(ei);
    bsum_k     <<<NB, 256, 0, s2>>>();
    finalize_k <<<NB, 256, 0, s2>>>();
    fill_k     <<<totBlocks, 256, 0, s2>>>(ei);
    cudaEventRecord(evJoin, s2);

    // layer 0 GEMM (independent of CSR)
    gemm_f16_k<<<gemmBlocks, 256, SMEM_BYTES>>>(x, W0, 0);

    // join: gather needs both CSR and hw
    cudaStreamWaitEvent(0, evJoin, 0);

    gather_k  <<<gathBlocks, 256>>>(b0, out, 0);
    // layer 1
    gemm_f16_k<<<gemmBlocks, 256, SMEM_BYTES>>>(x, W1, 1);
    gather_k  <<<gathBlocks, 256>>>(b1, out, 0);
    // layer 2
    gemm_f16_k<<<gemmBlocks, 256, SMEM_BYTES>>>(x, W2, 1);
    gather_k  <<<gathBlocks, 256>>>(b2, out, 1);
}

// round 12
// speedup vs baseline: 1.0168x; 1.0168x over previous
#include <cuda_runtime.h>
#include <cuda_fp16.h>
#include <cstdint>

#define N_NODES 50000
#define N_EDGES 600000
#define DIM 128
#define TOT_EDGES (N_EDGES + N_NODES)   // edges + self loops
#define NB 196                          // ceil(50000/256) scan blocks

// smem tiles: halves, row stride 136 (272B = 16B-aligned, conflict-free frags)
#define STRH 136                        // stride in halves
#define STRW 68                         // stride in u32 words
#define SMEM_BYTES (2 * 128 * STRH * 2) // As + Wt = 69632 B

// ---- scratch (device globals; no allocations allowed) ----
__device__ __half g_hw  [N_NODES * DIM];  // h @ W          (fp16)
__device__ __half g_act [N_NODES * DIM];  // relu(agg + b)  (fp16)
__device__ float  g_dinv[N_NODES];
__device__ int    g_deg   [N_NODES];
__device__ int    g_rowptr[N_NODES + 1];
__device__ int    g_cursor[N_NODES];
__device__ int    g_esrc  [TOT_EDGES];    // CSR-by-dst: src node per slot
__device__ float  g_enorm [TOT_EDGES];    // dinv[src]*dinv[dst] per slot

// ---- PDL helpers ----
__device__ __forceinline__ void pdl_trigger() {
    asm volatile("griddepcontrol.launch_dependents;");
}
__device__ __forceinline__ void pdl_wait() {
    asm volatile("griddepcontrol.wait;" ::: "memory");
}

// ---------------------------------------------------------------------------
// CSR build: deg init -> count -> scan+finalize -> fill
// ---------------------------------------------------------------------------
__global__ void deg_init_k() {
    pdl_trigger();
    int i = blockIdx.x * blockDim.x + threadIdx.x;
    if (i < N_NODES) g_deg[i] = 1;          // self loop
}

__global__ void deg_count_k(const int* __restrict__ ei) {
    pdl_trigger();
    int e4 = blockIdx.x * blockDim.x + threadIdx.x;   // int4 task
    if (e4 * 4 + 3 < N_EDGES) {
        int4 d = *(const int4*)(ei + N_EDGES + e4 * 4);   // external: pre-wait
        pdl_wait();
        if (d.x >= 0 && d.x < N_NODES) atomicAdd(&g_deg[d.x], 1);
        if (d.y >= 0 && d.y < N_NODES) atomicAdd(&g_deg[d.y], 1);
        if (d.z >= 0 && d.z < N_NODES) atomicAdd(&g_deg[d.z], 1);
        if (d.w >= 0 && d.w < N_NODES) atomicAdd(&g_deg[d.w], 1);
    } else {
        pdl_wait();
        for (int e = e4 * 4; e < N_EDGES; e++) {
            int d = ei[N_EDGES + e];
            if (d >= 0 && d < N_NODES) atomicAdd(&g_deg[d], 1);
        }
    }
}

// merged block-sum + finalize: each block sums all preceding degrees itself
__global__ void __launch_bounds__(256) scan_fin_k() {
    pdl_trigger();
    pdl_wait();
    __shared__ int sh[256];
    __shared__ int s_blkoff;
    int t = threadIdx.x;
    int i = blockIdx.x * 256 + t;

    // base offset = sum of deg[0 .. blockIdx*256)
    int local = 0;
    for (int j = t; j < blockIdx.x * 256; j += 256) local += g_deg[j];
    sh[t] = local;
    __syncthreads();
    for (int off = 128; off > 0; off >>= 1) {
        if (t < off) sh[t] += sh[t + off];
        __syncthreads();
    }
    if (t == 0) s_blkoff = sh[0];
    __syncthreads();

    // intra-block inclusive scan of own degrees
    int v = (i < N_NODES) ? g_deg[i] : 0;
    sh[t] = v;
    __syncthreads();
    for (int off = 1; off < 256; off <<= 1) {
        int x = (t >= off) ? sh[t - off] : 0;
        __syncthreads();
        sh[t] += x;
        __syncthreads();
    }
    if (i < N_NODES) {
        int start = s_blkoff + sh[t] - v;   // exclusive global prefix
        g_rowptr[i] = start;
        g_cursor[i] = start;
        g_dinv[i]   = rsqrtf((float)v);
        if (i == N_NODES - 1) g_rowptr[N_NODES] = start + v;
    }
}

__global__ void fill_k(const int* __restrict__ ei) {
    pdl_trigger();
    int e = blockIdx.x * blockDim.x + threadIdx.x;
    if (e >= TOT_EDGES) { pdl_wait(); return; }
    int s, d;
    if (e < N_EDGES) {
        s = ei[e];                           // external: pre-wait
        d = ei[N_EDGES + e];
        pdl_wait();
        if (s < 0 || s >= N_NODES || d < 0 || d >= N_NODES) return;
    } else {
        pdl_wait();
        s = d = e - N_EDGES;                 // self loop
    }
    int pos = atomicAdd(&g_cursor[d], 1);
    g_esrc[pos]  = s;
    g_enorm[pos] = g_dinv[s] * g_dinv[d];
}

// ---------------------------------------------------------------------------
// fp16 tensor-core GEMM: g_hw[N,128] (fp16) = src @ W[128,128]
//   use_agg=0: src = x (fp32);  use_agg=1: src = g_act (fp16)
// Full-K single-stage smem; mma.m16n8k16.f32.f16.f16.f32.
// W-tile load (external data) runs BEFORE pdl_wait -> overlaps predecessor.
// ---------------------------------------------------------------------------
extern __shared__ uint32_t s_dyn[];

__global__ void __launch_bounds__(256) gemm_f16_k(
    const float* __restrict__ A, const float* __restrict__ W, int use_agg)
{
    pdl_trigger();

    uint32_t* As = s_dyn;                 // [128][STRW] u32 (2 halves each)
    uint32_t* Wt = s_dyn + 128 * STRW;    // [128 n][STRW] u32, k contiguous

    const int tid   = threadIdx.x;
    const int lane  = tid & 31;
    const int wid   = tid >> 5;
    const int warpM = wid & 3;            // 0..3  -> 32-row strip
    const int warpN = wid >> 2;           // 0..1  -> 64-col strip
    const int g     = lane >> 2;          // groupID 0..7
    const int q     = lane & 3;           // thread-in-group 0..3
    const int row0  = blockIdx.x * 128;

    // ---- W load (independent of predecessor): transposed Wt[n][k] ----
#pragma unroll
    for (int t = 0; t < 16; t++) {
        int i  = tid + t * 256;           // 0..4095 tasks: (n, k-block of 4)
        int n  = i & 127;
        int kb = i >> 7;                  // 0..31
        int k0 = kb * 4;
        float w0 = W[(size_t)(k0 + 0) * DIM + n];
        float w1 = W[(size_t)(k0 + 1) * DIM + n];
        float w2 = W[(size_t)(k0 + 2) * DIM + n];
        float w3 = W[(size_t)(k0 + 3) * DIM + n];
        uint2 p;
        *(__half2*)&p.x = __float22half2_rn(make_float2(w0, w1));
        *(__half2*)&p.y = __float22half2_rn(make_float2(w2, w3));
        *(uint2*)&Wt[n * STRW + kb * 2] = p;
    }

    pdl_wait();   // predecessor (gather / fill) must be complete before A read

    // ---- load A (full K=128) as fp16 ----
    if (!use_agg) {
#pragma unroll
        for (int t = 0; t < 16; t++) {
            int i  = tid + t * 256;       // 0..4095 float4 tasks
            int r  = i >> 5;              // 0..127
            int c4 = (i & 31) * 4;        // 0..124
            int grow = row0 + r;
            float4 v = make_float4(0.f, 0.f, 0.f, 0.f);
            if (grow < N_NODES)
                v = *(const float4*)(A + (size_t)grow * DIM + c4);
            uint2 p;
            *(__half2*)&p.x = __float22half2_rn(make_float2(v.x, v.y));
            *(__half2*)&p.y = __float22half2_rn(make_float2(v.z, v.w));
            *(uint2*)&As[r * STRW + c4 / 2] = p;
        }
    } else {
#pragma unroll
        for (int t = 0; t < 8; t++) {
            int i  = tid + t * 256;       // 0..2047 uint4 tasks (8 halves)
            int r  = i >> 4;              // 0..127
            int c8 = (i & 15) * 8;        // 0..120
            int grow = row0 + r;
            uint4 raw = make_uint4(0, 0, 0, 0);
            if (grow < N_NODES)
                raw = *(const uint4*)(g_act + (size_t)grow * DIM + c8);
            *(uint4*)&As[r * STRW + c8 / 2] = raw;
        }
    }
    __syncthreads();

    // ---- mma: 8 k-steps of 16 ----
    float acc[2][8][4];
#pragma unroll
    for (int mt = 0; mt < 2; mt++)
#pragma unroll
        for (int nt = 0; nt < 8; nt++)
#pragma unroll
            for (int i = 0; i < 4; i++) acc[mt][nt][i] = 0.0f;

#pragma unroll
    for (int ks = 0; ks < 8; ++ks) {
        const int kw = ks * 8;            // u32 k-offset (16 halves)

        uint32_t a[2][4];
#pragma unroll
        for (int mt = 0; mt < 2; mt++) {
            int mb = warpM * 32 + mt * 16 + g;
            a[mt][0] = As[mb * STRW + kw + q];
            a[mt][1] = As[(mb + 8) * STRW + kw + q];
            a[mt][2] = As[mb * STRW + kw + q + 4];
            a[mt][3] = As[(mb + 8) * STRW + kw + q + 4];
        }
        uint32_t b[8][2];
#pragma unroll
        for (int nt = 0; nt < 8; nt++) {
            int n = warpN * 64 + nt * 8 + g;
            b[nt][0] = Wt[n * STRW + kw + q];
            b[nt][1] = Wt[n * STRW + kw + q + 4];
        }
#pragma unroll
        for (int mt = 0; mt < 2; mt++)
#pragma unroll
            for (int nt = 0; nt < 8; nt++) {
                asm volatile(
                    "mma.sync.aligned.m16n8k16.row.col.f32.f16.f16.f32 "
                    "{%0,%1,%2,%3}, {%4,%5,%6,%7}, {%8,%9}, {%0,%1,%2,%3};"
                    : "+f"(acc[mt][nt][0]), "+f"(acc[mt][nt][1]),
                      "+f"(acc[mt][nt][2]), "+f"(acc[mt][nt][3])
                    : "r"(a[mt][0]), "r"(a[mt][1]), "r"(a[mt][2]), "r"(a[mt][3]),
                      "r"(b[nt][0]), "r"(b[nt][1]));
            }
    }

    // ---- epilogue: write fp16 hw ----
#pragma unroll
    for (int mt = 0; mt < 2; mt++) {
        int r0 = row0 + warpM * 32 + mt * 16 + g;
        int r1 = r0 + 8;
#pragma unroll
        for (int nt = 0; nt < 8; nt++) {
            int col = warpN * 64 + nt * 8 + q * 2;
            if (r0 < N_NODES)
                *(__half2*)(g_hw + (size_t)r0 * DIM + col) =
                    __float22half2_rn(make_float2(acc[mt][nt][0], acc[mt][nt][1]));
            if (r1 < N_NODES)
                *(__half2*)(g_hw + (size_t)r1 * DIM + col) =
                    __float22half2_rn(make_float2(acc[mt][nt][2], acc[mt][nt][3]));
        }
    }
}

// ---------------------------------------------------------------------------
// gather: warp per dst node; lane owns 4 halves (8B) of the 256B row.
// bias load (external) before pdl_wait; CSR + hw reads after.
// ---------------------------------------------------------------------------
__global__ void __launch_bounds__(256) gather_k(
    const float* __restrict__ bias, float* __restrict__ out, int last)
{
    pdl_trigger();
    int w    = (blockIdx.x * blockDim.x + threadIdx.x) >> 5;
    int lane = threadIdx.x & 31;

    float4 acc = ((const float4*)bias)[lane];   // external: pre-wait
    pdl_wait();
    if (w >= N_NODES) return;

    int beg = g_rowptr[w];
    int end = g_rowptr[w + 1];

    const uint2* hw2 = (const uint2*)g_hw;   // 4 halves per lane-slot

    int j = beg;
    for (; j + 3 < end; j += 4) {
        int   s0 = g_esrc[j],      s1 = g_esrc[j + 1];
        int   s2 = g_esrc[j + 2],  s3 = g_esrc[j + 3];
        float n0 = g_enorm[j],     n1 = g_enorm[j + 1];
        float n2 = g_enorm[j + 2], n3 = g_enorm[j + 3];
        uint2 r0 = hw2[s0 * 32 + lane];
        uint2 r1 = hw2[s1 * 32 + lane];
        uint2 r2 = hw2[s2 * 32 + lane];
        uint2 r3 = hw2[s3 * 32 + lane];
        float2 a0 = __half22float2(*(__half2*)&r0.x), b0 = __half22float2(*(__half2*)&r0.y);
        float2 a1 = __half22float2(*(__half2*)&r1.x), b1 = __half22float2(*(__half2*)&r1.y);
        float2 a2 = __half22float2(*(__half2*)&r2.x), b2 = __half22float2(*(__half2*)&r2.y);
        float2 a3 = __half22float2(*(__half2*)&r3.x), b3 = __half22float2(*(__half2*)&r3.y);
        acc.x += a0.x * n0; acc.y += a0.y * n0; acc.z += b0.x * n0; acc.w += b0.y * n0;
        acc.x += a1.x * n1; acc.y += a1.y * n1; acc.z += b1.x * n1; acc.w += b1.y * n1;
        acc.x += a2.x * n2; acc.y += a2.y * n2; acc.z += b2.x * n2; acc.w += b2.y * n2;
        acc.x += a3.x * n3; acc.y += a3.y * n3; acc.z += b3.x * n3; acc.w += b3.y * n3;
    }
    for (; j < end; j++) {
        int   s0 = g_esrc[j];
        float n0 = g_enorm[j];
        uint2 r0 = hw2[s0 * 32 + lane];
        float2 a0 = __half22float2(*(__half2*)&r0.x), b0 = __half22float2(*(__half2*)&r0.y);
        acc.x += a0.x * n0; acc.y += a0.y * n0; acc.z += b0.x * n0; acc.w += b0.y * n0;
    }

    acc.x = fmaxf(acc.x, 0.f); acc.y = fmaxf(acc.y, 0.f);
    acc.z = fmaxf(acc.z, 0.f); acc.w = fmaxf(acc.w, 0.f);

    if (last) {
        ((float4*)out)[w * 32 + lane] = acc;
    } else {
        uint2 o;
        *(__half2*)&o.x = __float22half2_rn(make_float2(acc.x, acc.y));
        *(__half2*)&o.y = __float22half2_rn(make_float2(acc.z, acc.w));
        ((uint2*)g_act)[w * 32 + lane] = o;
    }
}

// ---------------------------------------------------------------------------
static void pdl_launch(const void* fn, int grid, int block, size_t smem,
                       void** args)
{
    cudaLaunchConfig_t cfg = {};
    cfg.gridDim  = dim3(grid, 1, 1);
    cfg.blockDim = dim3(block, 1, 1);
    cfg.dynamicSmemBytes = smem;
    cfg.stream = 0;
    cudaLaunchAttribute attr[1];
    attr[0].id = cudaLaunchAttributeProgrammaticStreamSerialization;
    attr[0].val.programmaticStreamSerializationAllowed = 1;
    cfg.attrs = attr;
    cfg.numAttrs = 1;
    cudaLaunchKernelExC(&cfg, fn, args);
}

extern "C" void kernel_launch(void* const* d_in, const int* in_sizes, int n_in,
                              void* d_out, int out_size)
{
    const float* x  = (const float*)d_in[0];
    const int*   ei = (const int*)d_in[1];     // edge_index int32 [2, E]
    const float* W0 = (const float*)d_in[2];
    const float* b0 = (const float*)d_in[3];
    const float* W1 = (const float*)d_in[4];
    const float* b1 = (const float*)d_in[5];
    const float* W2 = (const float*)d_in[6];
    const float* b2 = (const float*)d_in[7];
    float* out = (float*)d_out;

    static int inited = 0;
    if (!inited) {
        cudaFuncSetAttribute(gemm_f16_k,
            cudaFuncAttributeMaxDynamicSharedMemorySize, SMEM_BYTES);
        inited = 1;
    }

    const int cntBlocks  = (N_EDGES / 4 + 255) / 256;
    const int totBlocks  = (TOT_EDGES + 255) / 256;
    const int gemmBlocks = (N_NODES + 127) / 128;
    const int gathBlocks = (N_NODES * 32 + 255) / 256;   // warp per node

    int zero = 0, one = 1;

    // CSR build
    { void* a[] = {};                                pdl_launch((const void*)deg_init_k,  NB,         256, 0, a); }
    { void* a[] = {(void*)&ei};                      pdl_launch((const void*)deg_count_k, cntBlocks,  256, 0, a); }
    { void* a[] = {};                                pdl_launch((const void*)scan_fin_k,  NB,         256, 0, a); }
    { void* a[] = {(void*)&ei};                      pdl_launch((const void*)fill_k,      totBlocks,  256, 0, a); }

    // layer 0
    { void* a[] = {(void*)&x, (void*)&W0, &zero};    pdl_launch((const void*)gemm_f16_k, gemmBlocks, 256, SMEM_BYTES, a); }
    { void* a[] = {(void*)&b0, (void*)&out, &zero};  pdl_launch((const void*)gather_k,   gathBlocks, 256, 0, a); }
    // layer 1
    { void* a[] = {(void*)&x, (void*)&W1, &one};     pdl_launch((const void*)gemm_f16_k, gemmBlocks, 256, SMEM_BYTES, a); }
    { void* a[] = {(void*)&b1, (void*)&out, &zero};  pdl_launch((const void*)gather_k,   gathBlocks, 256, 0, a); }
    // layer 2
    { void* a[] = {(void*)&x, (void*)&W2, &one};     pdl_launch((const void*)gemm_f16_k, gemmBlocks, 256, SMEM_BYTES, a); }
    { void* a[] = {(void*)&b2, (void*)&out, &one};   pdl_launch((const void*)gather_k,   gathBlocks, 256, 0, a); }
}

// round 13
// speedup vs baseline: 1.0196x; 1.0027x over previous
#include <cuda_runtime.h>
#include <cuda_fp16.h>
#include <cstdint>

#define N_NODES 50000
#define N_EDGES 600000
#define DIM 128
#define TOT_EDGES (N_EDGES + N_NODES)   // edges + self loops
#define NB 196                          // ceil(50000/256) scan blocks

// smem tiles: halves, row stride 136 (272B = 16B-aligned, conflict-free frags)
#define STRH 136                        // stride in halves
#define STRW 68                         // stride in u32 words
#define SMEM_BYTES (2 * 128 * STRH * 2) // As + Wt = 69632 B

// ---- scratch (device globals; no allocations allowed) ----
__device__ __half g_hw  [N_NODES * DIM];  // h @ W          (fp16)
__device__ __half g_act [N_NODES * DIM];  // relu(agg + b)  (fp16)
__device__ float  g_dinv[N_NODES];
__device__ int    g_deg   [N_NODES];
__device__ int    g_rowptr[N_NODES + 1];
__device__ int    g_eoff  [N_EDGES];      // per-edge slot offset within dst row
__device__ int    g_esrc  [TOT_EDGES];    // CSR-by-dst: src node per slot

// ---- PDL helpers ----
__device__ __forceinline__ void pdl_trigger() {
    asm volatile("griddepcontrol.launch_dependents;");
}
__device__ __forceinline__ void pdl_wait() {
    asm volatile("griddepcontrol.wait;" ::: "memory");
}

// ---------------------------------------------------------------------------
// CSR build: deg init -> count (+slot offsets) -> scan+finalize -> fill
// ---------------------------------------------------------------------------
__global__ void deg_init_k() {
    pdl_trigger();
    int i = blockIdx.x * blockDim.x + threadIdx.x;
    if (i < N_NODES) g_deg[i] = 1;          // self loop takes slot 0
}

__global__ void deg_count_k(const int* __restrict__ ei) {
    pdl_trigger();
    int e4 = blockIdx.x * blockDim.x + threadIdx.x;   // int4 task (E%4==0)
    if (e4 * 4 >= N_EDGES) { pdl_wait(); return; }
    int4 d = *(const int4*)(ei + N_EDGES + e4 * 4);   // external: pre-wait
    pdl_wait();
    int4 off;
    off.x = (d.x >= 0 && d.x < N_NODES) ? atomicAdd(&g_deg[d.x], 1) : 0;
    off.y = (d.y >= 0 && d.y < N_NODES) ? atomicAdd(&g_deg[d.y], 1) : 0;
    off.z = (d.z >= 0 && d.z < N_NODES) ? atomicAdd(&g_deg[d.z], 1) : 0;
    off.w = (d.w >= 0 && d.w < N_NODES) ? atomicAdd(&g_deg[d.w], 1) : 0;
    *(int4*)(g_eoff + e4 * 4) = off;                  // coalesced
}

// merged block-sum + finalize: each block sums all preceding degrees itself;
// also writes the self-loop slot (slot 0 of each row).
__global__ void __launch_bounds__(256) scan_fin_k() {
    pdl_trigger();
    pdl_wait();
    __shared__ int sh[256];
    __shared__ int s_blkoff;
    int t = threadIdx.x;
    int i = blockIdx.x * 256 + t;

    // base offset = sum of deg[0 .. blockIdx*256)
    int local = 0;
    for (int j = t; j < blockIdx.x * 256; j += 256) local += g_deg[j];
    sh[t] = local;
    __syncthreads();
    for (int off = 128; off > 0; off >>= 1) {
        if (t < off) sh[t] += sh[t + off];
        __syncthreads();
    }
    if (t == 0) s_blkoff = sh[0];
    __syncthreads();

    // intra-block inclusive scan of own degrees
    int v = (i < N_NODES) ? g_deg[i] : 0;
    sh[t] = v;
    __syncthreads();
    for (int off = 1; off < 256; off <<= 1) {
        int x = (t >= off) ? sh[t - off] : 0;
        __syncthreads();
        sh[t] += x;
        __syncthreads();
    }
    if (i < N_NODES) {
        int start = s_blkoff + sh[t] - v;   // exclusive global prefix
        g_rowptr[i] = start;
        g_esrc[start] = i;                  // self loop at slot 0
        g_dinv[i]   = rsqrtf((float)v);
        if (i == N_NODES - 1) g_rowptr[N_NODES] = start + v;
    }
}

__global__ void fill_k(const int* __restrict__ ei) {
    pdl_trigger();
    int e = blockIdx.x * blockDim.x + threadIdx.x;
    if (e >= N_EDGES) { pdl_wait(); return; }
    int s = ei[e];                           // external: pre-wait
    int d = ei[N_EDGES + e];
    pdl_wait();
    if (s < 0 || s >= N_NODES || d < 0 || d >= N_NODES) return;
    g_esrc[g_rowptr[d] + g_eoff[e]] = s;     // single random 4B store
}

// ---------------------------------------------------------------------------
// fp16 tensor-core GEMM: g_hw[N,128] (fp16) = src @ W[128,128]
//   use_agg=0: src = x (fp32);  use_agg=1: src = g_act (fp16)
// Full-K single-stage smem; mma.m16n8k16.f32.f16.f16.f32.
// W-tile load (external data) runs BEFORE pdl_wait -> overlaps predecessor.
// ---------------------------------------------------------------------------
extern __shared__ uint32_t s_dyn[];

__global__ void __launch_bounds__(256) gemm_f16_k(
    const float* __restrict__ A, const float* __restrict__ W, int use_agg)
{
    pdl_trigger();

    uint32_t* As = s_dyn;                 // [128][STRW] u32 (2 halves each)
    uint32_t* Wt = s_dyn + 128 * STRW;    // [128 n][STRW] u32, k contiguous

    const int tid   = threadIdx.x;
    const int lane  = tid & 31;
    const int wid   = tid >> 5;
    const int warpM = wid & 3;            // 0..3  -> 32-row strip
    const int warpN = wid >> 2;           // 0..1  -> 64-col strip
    const int g     = lane >> 2;          // groupID 0..7
    const int q     = lane & 3;           // thread-in-group 0..3
    const int row0  = blockIdx.x * 128;

    // ---- W load (independent of predecessor): transposed Wt[n][k] ----
#pragma unroll
    for (int t = 0; t < 16; t++) {
        int i  = tid + t * 256;           // 0..4095 tasks: (n, k-block of 4)
        int n  = i & 127;
        int kb = i >> 7;                  // 0..31
        int k0 = kb * 4;
        float w0 = W[(size_t)(k0 + 0) * DIM + n];
        float w1 = W[(size_t)(k0 + 1) * DIM + n];
        float w2 = W[(size_t)(k0 + 2) * DIM + n];
        float w3 = W[(size_t)(k0 + 3) * DIM + n];
        uint2 p;
        *(__half2*)&p.x = __float22half2_rn(make_float2(w0, w1));
        *(__half2*)&p.y = __float22half2_rn(make_float2(w2, w3));
        *(uint2*)&Wt[n * STRW + kb * 2] = p;
    }

    pdl_wait();   // predecessor (gather) must be complete before A read

    // ---- load A (full K=128) as fp16 ----
    if (!use_agg) {
#pragma unroll
        for (int t = 0; t < 16; t++) {
            int i  = tid + t * 256;       // 0..4095 float4 tasks
            int r  = i >> 5;              // 0..127
            int c4 = (i & 31) * 4;        // 0..124
            int grow = row0 + r;
            float4 v = make_float4(0.f, 0.f, 0.f, 0.f);
            if (grow < N_NODES)
                v = *(const float4*)(A + (size_t)grow * DIM + c4);
            uint2 p;
            *(__half2*)&p.x = __float22half2_rn(make_float2(v.x, v.y));
            *(__half2*)&p.y = __float22half2_rn(make_float2(v.z, v.w));
            *(uint2*)&As[r * STRW + c4 / 2] = p;
        }
    } else {
#pragma unroll
        for (int t = 0; t < 8; t++) {
            int i  = tid + t * 256;       // 0..2047 uint4 tasks (8 halves)
            int r  = i >> 4;              // 0..127
            int c8 = (i & 15) * 8;        // 0..120
            int grow = row0 + r;
            uint4 raw = make_uint4(0, 0, 0, 0);
            if (grow < N_NODES)
                raw = *(const uint4*)(g_act + (size_t)grow * DIM + c8);
            *(uint4*)&As[r * STRW + c8 / 2] = raw;
        }
    }
    __syncthreads();

    // ---- mma: 8 k-steps of 16 ----
    float acc[2][8][4];
#pragma unroll
    for (int mt = 0; mt < 2; mt++)
#pragma unroll
        for (int nt = 0; nt < 8; nt++)
#pragma unroll
            for (int i = 0; i < 4; i++) acc[mt][nt][i] = 0.0f;

#pragma unroll
    for (int ks = 0; ks < 8; ++ks) {
        const int kw = ks * 8;            // u32 k-offset (16 halves)

        uint32_t a[2][4];
#pragma unroll
        for (int mt = 0; mt < 2; mt++) {
            int mb = warpM * 32 + mt * 16 + g;
            a[mt][0] = As[mb * STRW + kw + q];
            a[mt][1] = As[(mb + 8) * STRW + kw + q];
            a[mt][2] = As[mb * STRW + kw + q + 4];
            a[mt][3] = As[(mb + 8) * STRW + kw + q + 4];
        }
        uint32_t b[8][2];
#pragma unroll
        for (int nt = 0; nt < 8; nt++) {
            int n = warpN * 64 + nt * 8 + g;
            b[nt][0] = Wt[n * STRW + kw + q];
            b[nt][1] = Wt[n * STRW + kw + q + 4];
        }
#pragma unroll
        for (int mt = 0; mt < 2; mt++)
#pragma unroll
            for (int nt = 0; nt < 8; nt++) {
                asm volatile(
                    "mma.sync.aligned.m16n8k16.row.col.f32.f16.f16.f32 "
                    "{%0,%1,%2,%3}, {%4,%5,%6,%7}, {%8,%9}, {%0,%1,%2,%3};"
                    : "+f"(acc[mt][nt][0]), "+f"(acc[mt][nt][1]),
                      "+f"(acc[mt][nt][2]), "+f"(acc[mt][nt][3])
                    : "r"(a[mt][0]), "r"(a[mt][1]), "r"(a[mt][2]), "r"(a[mt][3]),
                      "r"(b[nt][0]), "r"(b[nt][1]));
            }
    }

    // ---- epilogue: write fp16 hw ----
#pragma unroll
    for (int mt = 0; mt < 2; mt++) {
        int r0 = row0 + warpM * 32 + mt * 16 + g;
        int r1 = r0 + 8;
#pragma unroll
        for (int nt = 0; nt < 8; nt++) {
            int col = warpN * 64 + nt * 8 + q * 2;
            if (r0 < N_NODES)
                *(__half2*)(g_hw + (size_t)r0 * DIM + col) =
                    __float22half2_rn(make_float2(acc[mt][nt][0], acc[mt][nt][1]));
            if (r1 < N_NODES)
                *(__half2*)(g_hw + (size_t)r1 * DIM + col) =
                    __float22half2_rn(make_float2(acc[mt][nt][2], acc[mt][nt][3]));
        }
    }
}

// ---------------------------------------------------------------------------
// gather: warp per dst node; lane owns 4 halves (8B) of the 256B row.
// norm computed on the fly: dinv[src]*dinv[dst] (bit-identical to stored).
// ---------------------------------------------------------------------------
__global__ void __launch_bounds__(256) gather_k(
    const float* __restrict__ bias, float* __restrict__ out, int last)
{
    pdl_trigger();
    int w    = (blockIdx.x * blockDim.x + threadIdx.x) >> 5;
    int lane = threadIdx.x & 31;

    float4 acc = ((const float4*)bias)[lane];   // external: pre-wait
    pdl_wait();
    if (w >= N_NODES) return;

    int beg = g_rowptr[w];
    int end = g_rowptr[w + 1];
    float dinv_w = g_dinv[w];

    const uint2* hw2 = (const uint2*)g_hw;   // 4 halves per lane-slot

    int j = beg;
    for (; j + 3 < end; j += 4) {
        int s0 = g_esrc[j],     s1 = g_esrc[j + 1];
        int s2 = g_esrc[j + 2], s3 = g_esrc[j + 3];
        float n0 = g_dinv[s0] * dinv_w, n1 = g_dinv[s1] * dinv_w;
        float n2 = g_dinv[s2] * dinv_w, n3 = g_dinv[s3] * dinv_w;
        uint2 r0 = hw2[s0 * 32 + lane];
        uint2 r1 = hw2[s1 * 32 + lane];
        uint2 r2 = hw2[s2 * 32 + lane];
        uint2 r3 = hw2[s3 * 32 + lane];
        float2 a0 = __half22float2(*(__half2*)&r0.x), b0 = __half22float2(*(__half2*)&r0.y);
        float2 a1 = __half22float2(*(__half2*)&r1.x), b1 = __half22float2(*(__half2*)&r1.y);
        float2 a2 = __half22float2(*(__half2*)&r2.x), b2 = __half22float2(*(__half2*)&r2.y);
        float2 a3 = __half22float2(*(__half2*)&r3.x), b3 = __half22float2(*(__half2*)&r3.y);
        acc.x += a0.x * n0; acc.y += a0.y * n0; acc.z += b0.x * n0; acc.w += b0.y * n0;
        acc.x += a1.x * n1; acc.y += a1.y * n1; acc.z += b1.x * n1; acc.w += b1.y * n1;
        acc.x += a2.x * n2; acc.y += a2.y * n2; acc.z += b2.x * n2; acc.w += b2.y * n2;
        acc.x += a3.x * n3; acc.y += a3.y * n3; acc.z += b3.x * n3; acc.w += b3.y * n3;
    }
    for (; j < end; j++) {
        int s0 = g_esrc[j];
        float n0 = g_dinv[s0] * dinv_w;
        uint2 r0 = hw2[s0 * 32 + lane];
        float2 a0 = __half22float2(*(__half2*)&r0.x), b0 = __half22float2(*(__half2*)&r0.y);
        acc.x += a0.x * n0; acc.y += a0.y * n0; acc.z += b0.x * n0; acc.w += b0.y * n0;
    }

    acc.x = fmaxf(acc.x, 0.f); acc.y = fmaxf(acc.y, 0.f);
    acc.z = fmaxf(acc.z, 0.f); acc.w = fmaxf(acc.w, 0.f);

    if (last) {
        ((float4*)out)[w * 32 + lane] = acc;
    } else {
        uint2 o;
        *(__half2*)&o.x = __float22half2_rn(make_float2(acc.x, acc.y));
        *(__half2*)&o.y = __float22half2_rn(make_float2(acc.z, acc.w));
        ((uint2*)g_act)[w * 32 + lane] = o;
    }
}

// ---------------------------------------------------------------------------
static void pdl_launch(const void* fn, int grid, int block, size_t smem,
                       void** args)
{
    cudaLaunchConfig_t cfg = {};
    cfg.gridDim  = dim3(grid, 1, 1);
    cfg.blockDim = dim3(block, 1, 1);
    cfg.dynamicSmemBytes = smem;
    cfg.stream = 0;
    cudaLaunchAttribute attr[1];
    attr[0].id = cudaLaunchAttributeProgrammaticStreamSerialization;
    attr[0].val.programmaticStreamSerializationAllowed = 1;
    cfg.attrs = attr;
    cfg.numAttrs = 1;
    cudaLaunchKernelExC(&cfg, fn, args);
}

extern "C" void kernel_launch(void* const* d_in, const int* in_sizes, int n_in,
                              void* d_out, int out_size)
{
    const float* x  = (const float*)d_in[0];
    const int*   ei = (const int*)d_in[1];     // edge_index int32 [2, E]
    const float* W0 = (const float*)d_in[2];
    const float* b0 = (const float*)d_in[3];
    const float* W1 = (const float*)d_in[4];
    const float* b1 = (const float*)d_in[5];
    const float* W2 = (const float*)d_in[6];
    const float* b2 = (const float*)d_in[7];
    float* out = (float*)d_out;

    static int inited = 0;
    if (!inited) {
        cudaFuncSetAttribute(gemm_f16_k,
            cudaFuncAttributeMaxDynamicSharedMemorySize, SMEM_BYTES);
        inited = 1;
    }

    const int cntBlocks  = (N_EDGES / 4 + 255) / 256;
    const int fillBlocks = (N_EDGES + 255) / 256;
    const int gemmBlocks = (N_NODES + 127) / 128;
    const int gathBlocks = (N_NODES * 32 + 255) / 256;   // warp per node

    int zero = 0, one = 1;

    // CSR build
    { void* a[] = {};                                pdl_launch((const void*)deg_init_k,  NB,         256, 0, a); }
    { void* a[] = {(void*)&ei};                      pdl_launch((const void*)deg_count_k, cntBlocks,  256, 0, a); }
    { void* a[] = {};                                pdl_launch((const void*)scan_fin_k,  NB,         256, 0, a); }
    { void* a[] = {(void*)&ei};                      pdl_launch((const void*)fill_k,      fillBlocks, 256, 0, a); }

    // layer 0
    { void* a[] = {(void*)&x, (void*)&W0, &zero};    pdl_launch((const void*)gemm_f16_k, gemmBlocks, 256, SMEM_BYTES, a); }
    { void* a[] = {(void*)&b0, (void*)&out, &zero};  pdl_launch((const void*)gather_k,   gathBlocks, 256, 0, a); }
    // layer 1
    { void* a[] = {(void*)&x, (void*)&W1, &one};     pdl_launch((const void*)gemm_f16_k, gemmBlocks, 256, SMEM_BYTES, a); }
    { void* a[] = {(void*)&b1, (void*)&out, &zero};  pdl_launch((const void*)gather_k,   gathBlocks, 256, 0, a); }
    // layer 2
    { void* a[] = {(void*)&x, (void*)&W2, &one};     pdl_launch((const void*)gemm_f16_k, gemmBlocks, 256, SMEM_BYTES, a); }
    { void* a[] = {(void*)&b2, (void*)&out, &one};   pdl_launch((const void*)gather_k,   gathBlocks, 256, 0, a); }
}